// round 4
// baseline (speedup 1.0000x reference)
#include <cuda_runtime.h>

// Closed-form normalization constants.
#define Y00f  0.28209479177387814f    // 1/(2*sqrt(pi))
#define N10f  0.48860251190291992f    // sqrt(3/(4pi))
#define N20f  0.63078313050504001f    // sqrt(5/(4pi))
#define C21f  (-1.09254843059207907f) // -(1/2)*sqrt(15/pi)
#define C22f  0.54627421529603953f    // (1/4)*sqrt(15/pi)
#define K20f  0.35355339059327379f    // 1/(2*sqrt(2))
#define K21f  0.20412414523193152f    // 1/(2*sqrt(6))
#define K30f  0.06415002990995843f    // 1/(9*sqrt(3))
#define K31f  0.04536092116208279f    // sqrt(1/486)
#define K32f  0.02028602047074832f    // sqrt(8/19440)

typedef unsigned long long u64;

// Per-entry premultipliers and source-coefficient indices.
// out = T6*b0 + T3*(b1*(2-r) + r*X1) + T2*(b5*L30 + G3*X2 + r^2*W)
// with L30 = (4/9)r^2 - 4r + 6, G3 = r*((8/3) - (4/9)r),
// W pre-scaled by 4/9 (since rho^2 = (4/9) r^2).
__constant__ float c_pre[17] = {
    2.0f * Y00f,                    // 0: b0   * c0   (T6)
    -(Y00f * K20f),                 // 1: b1n  * c1   (X1 + b1n)
    2.0f * Y00f * K20f,             // 2: b1d  * c1
    N10f * K21f,                    // 3: b2   * c3   (ct)
    -(N10f * K21f),                 // 4: b3   * c4   (cp)
    -(N10f * K21f),                 // 5: b4   * c2   (sp)
    Y00f * K30f,                    // 6: b5   * c5   (L30)
    N10f * K31f,                    // 7: b6   * c7   (ct)
    -(N10f * K31f),                 // 8: b7   * c8   (cp)
    -(N10f * K31f),                 // 9: b8   * c6   (sp)
    (2.0f / 3.0f) * N20f * K32f,    // 10: b9a * c11  (ct^2)   1.5*(4/9)
    -(2.0f / 9.0f) * N20f * K32f,   // 11: b9b * c11           0.5*(4/9)
    (4.0f / 9.0f) * C21f * K32f,    // 12: b10 * c12  (cp*ctst)
    (4.0f / 9.0f) * C21f * K32f,    // 13: b11 * c10  (sp*ctst)
    -(8.0f / 9.0f) * C22f * K32f,   // 14: b12m* c13  (sp^2)   -2*(4/9)
    (4.0f / 9.0f) * C22f * K32f,    // 15: b12s* c13
    (8.0f / 9.0f) * C22f * K32f     // 16: b13 * c9   (sp*cp)  2*(4/9)
};
__constant__ int c_idx[17] = {0, 1, 1, 3, 4, 2, 5, 7, 8, 6, 11, 11, 12, 10, 13, 13, 9};
// Packed radial-polynomial constants: entries 17..21.
__constant__ float c_rad[5] = {4.0f / 9.0f, -4.0f, 6.0f, -4.0f / 9.0f, 8.0f / 3.0f};

__device__ __forceinline__ u64 pk(float lo, float hi) {
    u64 r; asm("mov.b64 %0,{%1,%2};" : "=l"(r) : "f"(lo), "f"(hi)); return r;
}
__device__ __forceinline__ void upk(u64 v, float& lo, float& hi) {
    asm("mov.b64 {%0,%1},%2;" : "=f"(lo), "=f"(hi) : "l"(v));
}
__device__ __forceinline__ u64 f2mul(u64 a, u64 b) {
    u64 d; asm("mul.rn.f32x2 %0,%1,%2;" : "=l"(d) : "l"(a), "l"(b)); return d;
}
__device__ __forceinline__ u64 f2fma(u64 a, u64 b, u64 c) {
    u64 d; asm("fma.rn.f32x2 %0,%1,%2,%3;" : "=l"(d) : "l"(a), "l"(b), "l"(c)); return d;
}
__device__ __forceinline__ u64 f2add(u64 a, u64 b) {
    u64 d; asm("add.rn.f32x2 %0,%1,%2;" : "=l"(d) : "l"(a), "l"(b)); return d;
}

// Per-point MUFU-only prep.
struct P6 { float r, t, ct, st, cp, sp; };

__device__ __forceinline__ P6 prep(float r, float th, float ph) {
    P6 p;
    p.r = r;
    __sincosf(th, &p.st, &p.ct);
    __sincosf(ph, &p.sp, &p.cp);
    p.t = __expf(r * (-1.0f / 6.0f));   // e^{-r/6}
    return p;
}

// Packed evaluation of two points. sm[0..16] = coeffs, sm[17..21] = radial consts.
__device__ __forceinline__ u64 eval_pair(const P6& p0, const P6& p1, const u64* sm) {
    u64 R  = pk(p0.r,  p1.r),  T  = pk(p0.t,  p1.t);
    u64 CT = pk(p0.ct, p1.ct), ST = pk(p0.st, p1.st);
    u64 CP = pk(p0.cp, p1.cp), SP = pk(p0.sp, p1.sp);

    u64 T2 = f2mul(T, T), T3 = f2mul(T2, T), T6 = f2mul(T3, T3);
    u64 R2 = f2mul(R, R);
    u64 SPSP = f2mul(SP, SP), SPCP = f2mul(SP, CP);
    u64 CTCT = f2mul(CT, CT), ST2 = f2mul(ST, ST), CTST = f2mul(CT, ST);

    // n=2 block: B3 = b1*(2-r) + r*X1  (X1 = l=1 angular, n=2)
    u64 X1 = f2fma(CT, sm[3], f2mul(ST, f2fma(CP, sm[4], f2mul(SP, sm[5]))));
    u64 B3 = f2fma(R, f2add(X1, sm[1]), sm[2]);

    // n=3, l=0..1: P2 = b5*L30 + G3*X2
    u64 X2  = f2fma(CT, sm[7], f2mul(ST, f2fma(CP, sm[8], f2mul(SP, sm[9]))));
    u64 L30 = f2fma(R, f2fma(R, sm[17], sm[18]), sm[19]);  // (4/9)r^2 - 4r + 6
    u64 G3  = f2mul(R, f2fma(R, sm[20], sm[21]));          // r*((8/3) - (4/9)r)
    u64 P2  = f2fma(L30, sm[6], f2mul(G3, X2));

    // n=3, l=2 (W pre-scaled by 4/9): B2 = r^2 * W + P2
    u64 Z = f2fma(SPSP, sm[14], f2fma(SPCP, sm[16], sm[15]));
    u64 Y = f2fma(CP, sm[12], f2mul(SP, sm[13]));
    u64 W = f2fma(ST2, Z, f2fma(CTST, Y, f2fma(CTCT, sm[10], sm[11])));
    u64 B2 = f2fma(R2, W, P2);

    return f2fma(T6, sm[0], f2fma(T3, B3, f2mul(T2, B2)));
}

__global__ __launch_bounds__(128)
void orbital_eval_kernel(const float* __restrict__ pos,
                         const float* __restrict__ coeffs,
                         float* __restrict__ out,
                         int n4, int n) {
    __shared__ u64 sm[22];
    int tid = threadIdx.x;
    if (tid < 22) {
        float v = (tid < 17) ? c_pre[tid] * __ldg(&coeffs[c_idx[tid]])
                             : c_rad[tid - 17];
        sm[tid] = pk(v, v);
    }
    __syncthreads();

    int i = blockIdx.x * blockDim.x + tid;

    if (i < n4) {
        const float4* p4 = reinterpret_cast<const float4*>(pos);
        float4 va = p4[3 * i + 0];
        float4 vb = p4[3 * i + 1];
        float4 vc = p4[3 * i + 2];
        float2* o2 = reinterpret_cast<float2*>(out);

        // Pair 0: (va.x,va.y,va.z), (va.w,vb.x,vb.y)
        {
            P6 q0 = prep(va.x, va.y, va.z);
            P6 q1 = prep(va.w, vb.x, vb.y);
            u64 r01 = eval_pair(q0, q1, sm);
            float2 o; upk(r01, o.x, o.y);
            o2[2 * i] = o;
        }
        // Pair 1: (vb.z,vb.w,vc.x), (vc.y,vc.z,vc.w)
        {
            P6 q2 = prep(vb.z, vb.w, vc.x);
            P6 q3 = prep(vc.y, vc.z, vc.w);
            u64 r23 = eval_pair(q2, q3, sm);
            float2 o; upk(r23, o.x, o.y);
            o2[2 * i + 1] = o;
        }
    }

    // Scalar tail (n % 4 != 0): evaluate a duplicated pair, keep lo half.
    int tail = n - n4 * 4;
    if (i < tail) {
        int idx = n4 * 4 + i;
        P6 p = prep(pos[3 * idx], pos[3 * idx + 1], pos[3 * idx + 2]);
        u64 rr = eval_pair(p, p, sm);
        float lo, hi; upk(rr, lo, hi);
        out[idx] = lo;
    }
}

extern "C" void kernel_launch(void* const* d_in, const int* in_sizes, int n_in,
                              void* d_out, int out_size) {
    const float* pos    = (const float*)d_in[0];   // (2048, 4096, 3) fp32
    const float* coeffs = (const float*)d_in[1];   // (14,) fp32
    float* out          = (float*)d_out;           // (2048, 4096) fp32

    int n  = out_size;
    int n4 = n / 4;

    int threads = 128;
    int groups  = (n4 > 0) ? n4 : 1;
    int blocks  = (groups + threads - 1) / threads;
    orbital_eval_kernel<<<blocks, threads>>>(pos, coeffs, out, n4, n);
}

// round 5
// speedup vs baseline: 1.2373x; 1.2373x over previous
#include <cuda_runtime.h>

// Closed-form normalization constants.
#define Y00f  0.28209479177387814f    // 1/(2*sqrt(pi))
#define N10f  0.48860251190291992f    // sqrt(3/(4pi))
#define N20f  0.63078313050504001f    // sqrt(5/(4pi))
#define C21f  (-1.09254843059207907f) // -(1/2)*sqrt(15/pi)
#define C22f  0.54627421529603953f    // (1/4)*sqrt(15/pi)
#define K20f  0.35355339059327379f    // 1/(2*sqrt(2))
#define K21f  0.20412414523193152f    // 1/(2*sqrt(6))
#define K30f  0.06415002990995843f    // 1/(9*sqrt(3))
#define K31f  0.04536092116208279f    // sqrt(1/486)
#define K32f  0.02028602047074832f    // sqrt(8/19440)

typedef unsigned long long u64;

__device__ u64 g_A[14];   // pre-packed combined coefficients (lo==hi)

__device__ __forceinline__ u64 pk(float lo, float hi) {
    u64 r; asm("mov.b64 %0,{%1,%2};" : "=l"(r) : "f"(lo), "f"(hi)); return r;
}
__device__ __forceinline__ void upk(u64 v, float& lo, float& hi) {
    asm("mov.b64 {%0,%1},%2;" : "=f"(lo), "=f"(hi) : "l"(v));
}
__device__ __forceinline__ u64 f2mul(u64 a, u64 b) {
    u64 d; asm("mul.rn.f32x2 %0,%1,%2;" : "=l"(d) : "l"(a), "l"(b)); return d;
}
__device__ __forceinline__ u64 f2fma(u64 a, u64 b, u64 c) {
    u64 d; asm("fma.rn.f32x2 %0,%1,%2,%3;" : "=l"(d) : "l"(a), "l"(b), "l"(c)); return d;
}
__device__ __forceinline__ u64 f2add(u64 a, u64 b) {
    u64 d; asm("add.rn.f32x2 %0,%1,%2;" : "=l"(d) : "l"(a), "l"(b)); return d;
}

// One-warp setup: fold norms into coefficients, pack, store to global table.
__global__ void setup_coeffs_kernel(const float* __restrict__ coeffs) {
    if (threadIdx.x == 0) {
        float c[14];
#pragma unroll
        for (int k = 0; k < 14; k++) c[k] = coeffs[k];
        float ac[14];
        ac[0]  =  Y00f * 2.0f * c[0];
        ac[1]  =  Y00f * K20f * c[1];
        ac[2]  =  N10f * K21f * c[3];
        ac[3]  = -N10f * K21f * c[4];
        ac[4]  = -N10f * K21f * c[2];
        ac[5]  =  Y00f * K30f * c[5];
        ac[6]  =  N10f * K31f * c[7];
        ac[7]  = -N10f * K31f * c[8];
        ac[8]  = -N10f * K31f * c[6];
        ac[9]  =  N20f * K32f * c[11];
        ac[10] =  C21f * K32f * c[12];
        ac[11] =  C21f * K32f * c[10];
        ac[12] =  C22f * K32f * c[13];
        ac[13] =  C22f * K32f * c[9];
#pragma unroll
        for (int k = 0; k < 14; k++) g_A[k] = pk(ac[k], ac[k]);
    }
}

// Per-point scalar prep: MUFU ops + constant-immediate ops (FFMA-imm rt=1).
struct Prep { float r, t, ct, st, cp, sp, rho, tmr, fmr, l30, nspsq, ct2t; };

__device__ __forceinline__ Prep prep(float r, float th, float ph) {
    Prep p;
    p.r = r;
    __sincosf(th, &p.st, &p.ct);
    __sincosf(ph, &p.sp, &p.cp);
    p.t     = __expf(r * (-1.0f / 6.0f));      // e^{-r/6}
    p.rho   = r * (2.0f / 3.0f);
    p.tmr   = 2.0f - r;
    p.fmr   = 4.0f - p.rho;
    p.l30   = fmaf(p.rho - 6.0f, p.rho, 6.0f); // rho^2 - 6 rho + 6
    p.nspsq = p.sp * (-p.sp);                  // -sin^2(phi)
    p.ct2t  = fmaf(p.ct * p.ct, 1.5f, -0.5f);  // (3cos^2-1)/2
    return p;
}

// Packed evaluation of two points; a[] loads rematerialize as L1 hits.
__device__ __forceinline__ u64 eval_pair(const Prep& p0, const Prep& p1, const u64* a) {
    u64 R   = pk(p0.r,   p1.r),   T    = pk(p0.t,    p1.t);
    u64 CT  = pk(p0.ct,  p1.ct),  ST   = pk(p0.st,   p1.st);
    u64 CP  = pk(p0.cp,  p1.cp),  SP   = pk(p0.sp,   p1.sp);
    u64 RHO = pk(p0.rho, p1.rho), TMR  = pk(p0.tmr,  p1.tmr);
    u64 FMR = pk(p0.fmr, p1.fmr), L30  = pk(p0.l30,  p1.l30);
    u64 NSQ = pk(p0.nspsq, p1.nspsq), CT2T = pk(p0.ct2t, p1.ct2t);

    u64 T2 = f2mul(T, T), T3 = f2mul(T2, T), T6 = f2mul(T3, T3);
    u64 G3 = f2mul(FMR, RHO);           // (4-rho)*rho
    u64 Q  = f2mul(RHO, RHO);           // rho^2
    u64 C2P  = f2fma(CP, CP, NSQ);      // cos(2phi)
    u64 SPCP = f2mul(SP, CP);
    u64 S2P  = f2add(SPCP, SPCP);       // sin(2phi)
    u64 CTST = f2mul(CT, ST), ST2 = f2mul(ST, ST);

    // n=2 block (×t3)
    u64 X1 = f2fma(CP, a[3], f2mul(SP, a[4]));
    X1     = f2fma(CT, a[2], f2mul(ST, X1));
    u64 B3 = f2fma(TMR, a[1], f2mul(R, X1));

    // n=3, l=0..1 block (×t2)
    u64 X2 = f2fma(CP, a[7], f2mul(SP, a[8]));
    X2     = f2fma(CT, a[6], f2mul(ST, X2));
    u64 P2 = f2fma(L30, a[5], f2mul(G3, X2));

    // n=3, l=2 block
    u64 Y = f2fma(CP, a[10], f2mul(SP, a[11]));
    Y     = f2mul(CTST, Y);
    u64 Z = f2fma(C2P, a[12], f2mul(S2P, a[13]));
    u64 W = f2fma(ST2, Z, f2fma(CT2T, a[9], Y));
    u64 B2 = f2fma(Q, W, P2);

    return f2fma(T6, a[0], f2fma(T3, B3, f2mul(T2, B2)));
}

// Scalar path (tail only).
__device__ __forceinline__ float eval1(const Prep& p, const u64* a) {
    u64 rr = eval_pair(p, p, a);
    float lo, hi; upk(rr, lo, hi);
    return lo;
}

__global__ __launch_bounds__(128)
void orbital_eval_kernel(const float* __restrict__ pos,
                         float* __restrict__ out,
                         int n8, int n) {
    int i = blockIdx.x * blockDim.x + threadIdx.x;

    // Pre-packed combined coefficients; ptxas keeps these as L1-broadcast
    // reloads near uses (validated in R3: regs stay ~34).
    u64 a[14];
    {
        const ulonglong2* Ap = reinterpret_cast<const ulonglong2*>(g_A);
#pragma unroll
        for (int k = 0; k < 7; k++) {
            ulonglong2 v = __ldg(&Ap[k]);
            a[2 * k]     = v.x;
            a[2 * k + 1] = v.y;
        }
    }

    if (i < n8) {
        const float4* p4 = reinterpret_cast<const float4*>(pos);
        // 6 front-batched 128-bit loads: 8 points.
        float4 v0 = p4[6 * i + 0];
        float4 v1 = p4[6 * i + 1];
        float4 v2 = p4[6 * i + 2];
        float4 v3 = p4[6 * i + 3];
        float4 v4 = p4[6 * i + 4];
        float4 v5 = p4[6 * i + 5];

        float4* o4 = reinterpret_cast<float4*>(out);

        // Points 0..3 from v0,v1,v2
        {
            Prep q0 = prep(v0.x, v0.y, v0.z);
            Prep q1 = prep(v0.w, v1.x, v1.y);
            u64 r01 = eval_pair(q0, q1, a);
            Prep q2 = prep(v1.z, v1.w, v2.x);
            Prep q3 = prep(v2.y, v2.z, v2.w);
            u64 r23 = eval_pair(q2, q3, a);
            float4 o;
            upk(r01, o.x, o.y);
            upk(r23, o.z, o.w);
            o4[2 * i] = o;
        }
        // Points 4..7 from v3,v4,v5
        {
            Prep q0 = prep(v3.x, v3.y, v3.z);
            Prep q1 = prep(v3.w, v4.x, v4.y);
            u64 r01 = eval_pair(q0, q1, a);
            Prep q2 = prep(v4.z, v4.w, v5.x);
            Prep q3 = prep(v5.y, v5.z, v5.w);
            u64 r23 = eval_pair(q2, q3, a);
            float4 o;
            upk(r01, o.x, o.y);
            upk(r23, o.z, o.w);
            o4[2 * i + 1] = o;
        }
    }

    // Scalar tail (n % 8 != 0)
    int tail = n - n8 * 8;
    if (i < tail) {
        int idx = n8 * 8 + i;
        Prep p = prep(pos[3 * idx], pos[3 * idx + 1], pos[3 * idx + 2]);
        out[idx] = eval1(p, a);
    }
}

extern "C" void kernel_launch(void* const* d_in, const int* in_sizes, int n_in,
                              void* d_out, int out_size) {
    const float* pos    = (const float*)d_in[0];   // (2048, 4096, 3) fp32
    const float* coeffs = (const float*)d_in[1];   // (14,) fp32
    float* out          = (float*)d_out;           // (2048, 4096) fp32

    int n  = out_size;
    int n8 = n / 8;

    setup_coeffs_kernel<<<1, 32>>>(coeffs);

    int threads = 128;
    int groups  = (n8 > 0) ? n8 : 1;
    int blocks  = (groups + threads - 1) / threads;
    orbital_eval_kernel<<<blocks, threads>>>(pos, out, n8, n);
}